// round 10
// baseline (speedup 1.0000x reference)
#include <cuda_runtime.h>
#include <cuda_bf16.h>
#include <cstdint>

#define NCTX 4096
#define DM   512
#define NB   2
#define LDKT (NB*NCTX)

// Scratch
__device__ __nv_bfloat16 g_xhi[(size_t)NB*NCTX*DM];
__device__ __nv_bfloat16 g_xlo[(size_t)NB*NCTX*DM];
__device__ __nv_bfloat16 g_Whi[(size_t)DM*DM];
__device__ __nv_bfloat16 g_Wlo[(size_t)DM*DM];
__device__ __nv_bfloat16 g_Khi[(size_t)NB*NCTX*DM];
__device__ __nv_bfloat16 g_Klo[(size_t)NB*NCTX*DM];
__device__ float g_Kt [(size_t)DM*NB*NCTX];    // tf32-rounded K^T
__device__ float g_S  [(size_t)NB*NCTX*NCTX];  // scores -> unnormalized probs
__device__ float g_inv[(size_t)NB*NCTX];       // 1 / rowsum(exp)

// ---------------------------------------------------------------------------
// helpers
// ---------------------------------------------------------------------------
__device__ __forceinline__ uint32_t s2u(const void* p){
  uint32_t a;
  asm("{ .reg .u64 t; cvta.to.shared.u64 t, %1; cvt.u32.u64 %0, t; }" : "=r"(a) : "l"(p));
  return a;
}
__device__ __forceinline__ float tf32r(float x){
  uint32_t u; asm("cvt.rna.tf32.f32 %0, %1;" : "=r"(u) : "f"(x));
  return __uint_as_float(u);
}
__device__ __forceinline__ void ldsm4(uint32_t* r, uint32_t addr){
  asm volatile("ldmatrix.sync.aligned.m8n8.x4.shared.b16 {%0,%1,%2,%3}, [%4];"
    : "=r"(r[0]), "=r"(r[1]), "=r"(r[2]), "=r"(r[3]) : "r"(addr));
}
__device__ __forceinline__ void mma8(float* c, const uint32_t* a, const uint32_t* b){
  asm volatile("mma.sync.aligned.m16n8k8.row.col.f32.tf32.tf32.f32 "
    "{%0,%1,%2,%3}, {%4,%5,%6,%7}, {%8,%9}, {%0,%1,%2,%3};"
    : "+f"(c[0]), "+f"(c[1]), "+f"(c[2]), "+f"(c[3])
    : "r"(a[0]), "r"(a[1]), "r"(a[2]), "r"(a[3]), "r"(b[0]), "r"(b[1]));
}
__device__ __forceinline__ void bmma(float* c, const uint32_t* a, const uint32_t* b){
  asm volatile("mma.sync.aligned.m16n8k16.row.col.f32.bf16.bf16.f32 "
    "{%0,%1,%2,%3}, {%4,%5,%6,%7}, {%8,%9}, {%0,%1,%2,%3};"
    : "+f"(c[0]), "+f"(c[1]), "+f"(c[2]), "+f"(c[3])
    : "r"(a[0]), "r"(a[1]), "r"(a[2]), "r"(a[3]), "r"(b[0]), "r"(b[1]));
}
__device__ __forceinline__ void cp16(uint32_t d, const void* s){
  asm volatile("cp.async.cg.shared.global [%0], [%1], 16;" :: "r"(d), "l"(s));
}
__device__ __forceinline__ void cp_commit(){
  asm volatile("cp.async.commit_group;" ::: "memory");
}
template<int N> __device__ __forceinline__ void cp_wait(){
  asm volatile("cp.async.wait_group %0;" :: "n"(N) : "memory");
}

// ===========================================================================
// bf16 split (3-MMA) GEMM, 256 threads: C[128x128] = A * B^T (hi/lo inputs)
// BK=32, 2 stages, smem pitch 80 B.  (identical to R7's proven kernel)
// ===========================================================================
#define BT_TILE  10240
#define BT_STAGE (4*BT_TILE)

template<class EPI>
__device__ __forceinline__ void bgemm_split(
    const __nv_bfloat16* __restrict__ Ah, const __nv_bfloat16* __restrict__ Al, int lda,
    const __nv_bfloat16* __restrict__ Bh, const __nv_bfloat16* __restrict__ Bl, int ldb,
    int m0, int n0, int k1, EPI&& epi)
{
  extern __shared__ __align__(16) char sd[];
  const int t = threadIdx.x, l = t & 31, w = t >> 5;
  const int wm = w & 3, wn = w >> 2;
  const int row = t >> 1, seg = (t & 1) * 16;
  const uint32_t sb = s2u(sd);
  const uint32_t soff = (uint32_t)row*80 + (t & 1)*32;

  const __nv_bfloat16* pAh = Ah + (size_t)(m0 + row)*lda + seg;
  const __nv_bfloat16* pAl = Al + (size_t)(m0 + row)*lda + seg;
  const __nv_bfloat16* pBh = Bh + (size_t)(n0 + row)*ldb + seg;
  const __nv_bfloat16* pBl = Bl + (size_t)(n0 + row)*ldb + seg;

  const int nch = k1 >> 5;
  auto load_stage = [&](int c){
    const int kb = c << 5;
    const uint32_t st = sb + (c & 1)*BT_STAGE + soff;
    cp16(st,               pAh + kb); cp16(st + 16,             pAh + kb + 8);
    cp16(st +   BT_TILE,   pAl + kb); cp16(st +   BT_TILE + 16, pAl + kb + 8);
    cp16(st + 2*BT_TILE,   pBh + kb); cp16(st + 2*BT_TILE + 16, pBh + kb + 8);
    cp16(st + 3*BT_TILE,   pBl + kb); cp16(st + 3*BT_TILE + 16, pBl + kb + 8);
  };
  load_stage(0);
  cp_commit();

  const uint32_t aoff = (uint32_t)(wm*32 + (l & 15))*80 + ((l >> 4) & 1)*16;
  const uint32_t boff = (uint32_t)(wn*64 + (l & 7) + ((l >> 4) & 1)*8)*80
                      + ((l >> 3) & 1)*16;

  float acc[2][8][4] = {};

  for (int c = 0; c < nch; c++){
    cp_wait<0>();
    __syncthreads();
    if (c + 1 < nch) load_stage(c + 1);
    cp_commit();

    const uint32_t base = sb + (c & 1)*BT_STAGE;
    const uint32_t uAh = base + aoff,             uAl = uAh + BT_TILE;
    const uint32_t uBh = base + 2*BT_TILE + boff, uBl = uBh + BT_TILE;

    #pragma unroll
    for (int kf = 0; kf < 2; kf++){
      const uint32_t ko = kf*32;
      uint32_t ah[2][4], al[2][4];
      ldsm4(ah[0], uAh + ko);  ldsm4(ah[1], uAh + ko + 16*80);
      ldsm4(al[0], uAl + ko);  ldsm4(al[1], uAl + ko + 16*80);
      #pragma unroll
      for (int nf2 = 0; nf2 < 4; nf2++){
        uint32_t bh[4], bl[4];
        ldsm4(bh, uBh + ko + nf2*16*80);
        ldsm4(bl, uBl + ko + nf2*16*80);
        #pragma unroll
        for (int mf = 0; mf < 2; mf++){
          bmma(acc[mf][2*nf2],     ah[mf], bh);
          bmma(acc[mf][2*nf2 + 1], ah[mf], bh + 2);
          bmma(acc[mf][2*nf2],     ah[mf], bl);
          bmma(acc[mf][2*nf2 + 1], ah[mf], bl + 2);
          bmma(acc[mf][2*nf2],     al[mf], bh);
          bmma(acc[mf][2*nf2 + 1], al[mf], bh + 2);
        }
      }
    }
  }
  epi(acc);
}

// ===========================================================================
// tf32 single GEMM, 256 threads: C[128 x 64] = A * B^T. 4 stages.
// 8 warps = 4(M) x 2(N); warp tile 32 x 32. smem pitch 80 B.
// ===========================================================================
#define A_T6 10240                 // 128 rows * 80 B
#define B_T6 5120                  // 64 rows * 80 B
#define STG6 (A_T6 + B_T6)

template<int STAGES, class EPI>
__device__ __forceinline__ void tgemm64(
    const float* __restrict__ A, int lda,
    const float* __restrict__ B, int ldb,
    int m0, int n0, int k0, int k1, EPI&& epi)
{
  extern __shared__ __align__(16) char sd[];
  const int t = threadIdx.x, l = t & 31, w = t >> 5;
  const int wm = w & 3, wn = w >> 2;
  const uint32_t sb = s2u(sd);

  const int arow = t >> 1, acol = (t & 1) * 8;
  const uint32_t soA = (uint32_t)arow*80 + (t & 1)*32;
  const float* pA = A + (size_t)(m0 + arow)*lda + acol;
  const int brow = t >> 2, bcol = (t & 3) * 4;
  const uint32_t soB = (uint32_t)brow*80 + (t & 3)*16;
  const float* pB = B + (size_t)(n0 + brow)*ldb + bcol;

  const int nch = (k1 - k0) >> 4;
  auto load_stage = [&](int c){
    const int kb = k0 + (c << 4);
    const uint32_t st = sb + (c % STAGES)*STG6;
    cp16(st + soA,        pA + kb);  cp16(st + soA + 16, pA + kb + 4);
    cp16(st + A_T6 + soB, pB + kb);
  };
  #pragma unroll
  for (int s = 0; s < STAGES-1; s++){
    if (s < nch) load_stage(s);
    cp_commit();
  }

  const int rowA = (l & 7) + ((l >> 3) & 1) * 8;
  const int colA = ((l >> 4) & 1) * 4;
  const int rowB = (l & 7) + ((l >> 4) & 1) * 8;
  const int colB = ((l >> 3) & 1) * 4;
  const uint32_t aoff = (uint32_t)((wm*32 + rowA)*20 + colA) * 4;
  const uint32_t boff = (uint32_t)((wn*32 + rowB)*20 + colB) * 4;

  float acc[2][4][4] = {};

  for (int c = 0; c < nch; c++){
    cp_wait<STAGES-2>();
    __syncthreads();
    const int cn = c + STAGES - 1;
    if (cn < nch) load_stage(cn);
    cp_commit();

    const uint32_t base = sb + (c % STAGES)*STG6;
    const uint32_t uA = base + aoff;
    const uint32_t uB = base + A_T6 + boff;

    #pragma unroll
    for (int kf = 0; kf < 2; kf++){
      const uint32_t ko = kf * 32;
      uint32_t a[2][4];
      ldsm4(a[0], uA + ko);
      ldsm4(a[1], uA + ko + 16*80);
      #pragma unroll
      for (int nf2 = 0; nf2 < 2; nf2++){
        uint32_t b[4];
        ldsm4(b, uB + ko + nf2*16*80);
        #pragma unroll
        for (int mf = 0; mf < 2; mf++){
          mma8(acc[mf][2*nf2],     a[mf], b);
          mma8(acc[mf][2*nf2 + 1], a[mf], b + 2);
        }
      }
    }
  }
  epi(acc);
}

// plain store epilogue (128x128 bf16 gemm)
__device__ __forceinline__ void epi_store(float (&acc)[2][8][4],
                                          float* __restrict__ C, int ldc,
                                          int m0, int n0)
{
  const int t = threadIdx.x, l = t & 31, w = t >> 5;
  const int wm = w & 3, wn = w >> 2;
  #pragma unroll
  for (int mf = 0; mf < 2; mf++){
    const int r0 = m0 + wm*32 + mf*16 + (l >> 2);
    #pragma unroll
    for (int nf = 0; nf < 8; nf++){
      const int cc = n0 + wn*64 + nf*8 + 2*(l & 3);
      *(float2*)&C[(size_t)r0*ldc + cc]     = make_float2(acc[mf][nf][0], acc[mf][nf][1]);
      *(float2*)&C[(size_t)(r0+8)*ldc + cc] = make_float2(acc[mf][nf][2], acc[mf][nf][3]);
    }
  }
}

// ---------------------------------------------------------------------------
// Kernels
// ---------------------------------------------------------------------------
__global__ void __launch_bounds__(256)
k_prep(const float* __restrict__ x, const float* __restrict__ W)
{
  const size_t nx = (size_t)NB*NCTX*DM/4, nw = (size_t)DM*DM/4;
  for (size_t i = blockIdx.x*256 + threadIdx.x; i < nx + nw; i += (size_t)gridDim.x*256){
    float4 v;
    __nv_bfloat16* hi; __nv_bfloat16* lo; size_t j;
    if (i < nx){ v = ((const float4*)x)[i];      hi = g_xhi; lo = g_xlo; j = i; }
    else       { v = ((const float4*)W)[i - nx]; hi = g_Whi; lo = g_Wlo; j = i - nx; }
    __nv_bfloat16 hx = __float2bfloat16_rn(v.x), hy = __float2bfloat16_rn(v.y);
    __nv_bfloat16 hz = __float2bfloat16_rn(v.z), hw = __float2bfloat16_rn(v.w);
    __nv_bfloat162 h01; h01.x = hx; h01.y = hy;
    __nv_bfloat162 h23; h23.x = hz; h23.y = hw;
    __nv_bfloat162 l01; l01.x = __float2bfloat16_rn(v.x - __bfloat162float(hx));
                        l01.y = __float2bfloat16_rn(v.y - __bfloat162float(hy));
    __nv_bfloat162 l23; l23.x = __float2bfloat16_rn(v.z - __bfloat162float(hz));
                        l23.y = __float2bfloat16_rn(v.w - __bfloat162float(hw));
    ((__nv_bfloat162*)hi)[2*j]     = h01;
    ((__nv_bfloat162*)hi)[2*j + 1] = h23;
    ((__nv_bfloat162*)lo)[2*j]     = l01;
    ((__nv_bfloat162*)lo)[2*j + 1] = l23;
  }
}

__global__ void __launch_bounds__(256, 2)
k_proj()
{
  const int n0 = blockIdx.x*128, m0 = blockIdx.y*128;
  bgemm_split(g_xhi, g_xlo, DM, g_Whi, g_Wlo, DM, m0, n0, DM,
    [&](float (&acc)[2][8][4]){
      const int t = threadIdx.x, l = t & 31, w = t >> 5;
      const int wm = w & 3, wn = w >> 2;
      #pragma unroll
      for (int mf = 0; mf < 2; mf++){
        const int r0 = m0 + wm*32 + mf*16 + (l >> 2);
        #pragma unroll
        for (int nf = 0; nf < 8; nf++){
          const int cc = n0 + wn*64 + nf*8 + 2*(l & 3);
          #pragma unroll
          for (int hh = 0; hh < 2; hh++){
            const int r = r0 + hh*8;
            const float v0 = acc[mf][nf][2*hh], v1 = acc[mf][nf][2*hh+1];
            __nv_bfloat16 h0 = __float2bfloat16_rn(v0), h1 = __float2bfloat16_rn(v1);
            __nv_bfloat162 hp; hp.x = h0; hp.y = h1;
            __nv_bfloat162 lp;
            lp.x = __float2bfloat16_rn(v0 - __bfloat162float(h0));
            lp.y = __float2bfloat16_rn(v1 - __bfloat162float(h1));
            const size_t ki = (size_t)r*DM + cc;
            *(__nv_bfloat162*)&g_Khi[ki] = hp;
            *(__nv_bfloat162*)&g_Klo[ki] = lp;
            g_Kt[(size_t)cc    *LDKT + r] = tf32r(v0);
            g_Kt[(size_t)(cc+1)*LDKT + r] = tf32r(v1);
          }
        }
      }
    });
}

__global__ void __launch_bounds__(256, 2)
k_scores()
{
  const int b  = blockIdx.z;
  const int n0 = blockIdx.x*128, m0 = blockIdx.y*128;
  if (n0 > m0) return;
  const size_t off = (size_t)b*NCTX*DM;
  float* Sb = g_S + (size_t)b*NCTX*NCTX;
  bgemm_split(g_xhi + off, g_xlo + off, DM, g_Khi + off, g_Klo + off, DM,
    m0, n0, DM,
    [&](float (&acc)[2][8][4]){ epi_store(acc, Sb, NCTX, m0, n0); });
}

// ---------------------------------------------------------------------------
// softmax: S <- tf32(exp(S)); g_inv = 1/rowsum; zero-fill to 128 boundary
// ---------------------------------------------------------------------------
__device__ __forceinline__ float blk_sum(float v)
{
  __shared__ float sm[8];
  const int lane = threadIdx.x & 31, w = threadIdx.x >> 5;
  #pragma unroll
  for (int o = 16; o; o >>= 1) v += __shfl_xor_sync(0xffffffffu, v, o);
  if (lane == 0) sm[w] = v;
  __syncthreads();
  float r = sm[0];
  #pragma unroll
  for (int i = 1; i < 8; i++) r += sm[i];
  return r;
}

__global__ void __launch_bounds__(256)
k_softmax()
{
  const int row = blockIdx.x;
  const int q   = row & (NCTX - 1);
  float* p = g_S + (size_t)row * NCTX;
  const int len  = q + 1;
  const int len4 = len >> 2;
  float4* p4 = (float4*)p;

  float s = 0.f;
  for (int i = threadIdx.x; i < len4; i += 256){
    float4 v = p4[i];
    v.x = __expf(v.x); v.y = __expf(v.y);
    v.z = __expf(v.z); v.w = __expf(v.w);
    s += (v.x + v.y) + (v.z + v.w);
    v.x = tf32r(v.x); v.y = tf32r(v.y);
    v.z = tf32r(v.z); v.w = tf32r(v.w);
    p4[i] = v;
  }
  for (int i = (len4 << 2) + threadIdx.x; i < len; i += 256){
    float e = __expf(p[i]);
    s += e;
    p[i] = tf32r(e);
  }
  s = blk_sum(s);
  if (threadIdx.x == 0) g_inv[row] = 1.f / s;

  const int lenUp = (len + 127) & ~127;
  for (int i = len + threadIdx.x; i < lenUp; i += 256) p[i] = 0.f;
}

// ---------------------------------------------------------------------------
// out = x + (P @ K) * inv.  256 equal CTAs: each does m-tiles (pair, 31-pair)
// over a 64-wide n strip. No atomics, no split-K partials.
// ---------------------------------------------------------------------------
__global__ void __launch_bounds__(256, 2)
k_out_tc(const float* __restrict__ x, float* __restrict__ out)
{
  const int b    = blockIdx.z;
  const int n0   = blockIdx.x*64;       // 8 strips
  const int pair = blockIdx.y;          // 0..15
  const float* Pb = g_S  + (size_t)b*NCTX*NCTX;
  const float* Bt = g_Kt + (size_t)b*NCTX;

  #pragma unroll
  for (int s = 0; s < 2; s++){
    const int i  = s ? (31 - pair) : pair;
    const int m0 = i*128;
    tgemm64<4>(Pb, NCTX, Bt, LDKT, m0, n0, 0, m0 + 128,
      [&](float (&acc)[2][4][4]){
        const int t = threadIdx.x, l = t & 31, w = t >> 5;
        const int wm = w & 3, wn = w >> 2;
        #pragma unroll
        for (int mf = 0; mf < 2; mf++){
          const int r0 = m0 + wm*32 + mf*16 + (l >> 2);
          const float inv0 = g_inv[b*NCTX + r0];
          const float inv1 = g_inv[b*NCTX + r0 + 8];
          #pragma unroll
          for (int nf = 0; nf < 4; nf++){
            const int cc = n0 + wn*32 + nf*8 + 2*(l & 3);
            const size_t i0 = (size_t)b*NCTX*DM + (size_t)r0*DM + cc;
            const size_t i1 = i0 + (size_t)8*DM;
            *(float2*)&out[i0] = make_float2(acc[mf][nf][0]*inv0 + x[i0],
                                             acc[mf][nf][1]*inv0 + x[i0+1]);
            *(float2*)&out[i1] = make_float2(acc[mf][nf][2]*inv1 + x[i1],
                                             acc[mf][nf][3]*inv1 + x[i1+1]);
          }
        }
      });
  }
}

// ---------------------------------------------------------------------------
extern "C" void kernel_launch(void* const* d_in, const int* in_sizes, int n_in,
                              void* d_out, int out_size)
{
  const float* x = (const float*)d_in[0];
  const float* W = (const float*)d_in[1];
  float* out = (float*)d_out;

  const int SMEM_BF = 2 * BT_STAGE;      // 81920
  const int SMEM6   = 4 * STG6;          // 61440
  cudaFuncSetAttribute(k_proj,   cudaFuncAttributeMaxDynamicSharedMemorySize, SMEM_BF);
  cudaFuncSetAttribute(k_scores, cudaFuncAttributeMaxDynamicSharedMemorySize, SMEM_BF);
  cudaFuncSetAttribute(k_out_tc, cudaFuncAttributeMaxDynamicSharedMemorySize, SMEM6);

  k_prep   <<<1184, 256>>>(x, W);
  k_proj   <<<dim3(4, 64),      256, SMEM_BF>>>();
  k_scores <<<dim3(32, 32, NB), 256, SMEM_BF>>>();
  k_softmax<<<NB * NCTX, 256>>>();
  k_out_tc <<<dim3(8, 16, NB),  256, SMEM6>>>(x, out);
}

// round 11
// speedup vs baseline: 1.1274x; 1.1274x over previous
#include <cuda_runtime.h>
#include <cuda_bf16.h>
#include <cstdint>

#define NCTX 4096
#define DM   512
#define NB   2
#define LDKT (NB*NCTX)

// Scratch
__device__ __nv_bfloat16 g_xhi[(size_t)NB*NCTX*DM];
__device__ __nv_bfloat16 g_xlo[(size_t)NB*NCTX*DM];
__device__ __nv_bfloat16 g_Whi[(size_t)DM*DM];
__device__ __nv_bfloat16 g_Wlo[(size_t)DM*DM];
__device__ __nv_bfloat16 g_Khi[(size_t)NB*NCTX*DM];
__device__ __nv_bfloat16 g_Klo[(size_t)NB*NCTX*DM];
__device__ __nv_bfloat16 g_Ktb[(size_t)DM*NB*NCTX];   // bf16 K^T
__device__ float         g_S  [(size_t)NB*NCTX*NCTX]; // fp32 scores
__device__ __nv_bfloat16 g_Pb [(size_t)NB*NCTX*NCTX]; // bf16 unnormalized probs
__device__ float         g_inv[(size_t)NB*NCTX];      // 1 / rowsum(exp)

// ---------------------------------------------------------------------------
// helpers
// ---------------------------------------------------------------------------
__device__ __forceinline__ uint32_t s2u(const void* p){
  uint32_t a;
  asm("{ .reg .u64 t; cvta.to.shared.u64 t, %1; cvt.u32.u64 %0, t; }" : "=r"(a) : "l"(p));
  return a;
}
__device__ __forceinline__ void ldsm4(uint32_t* r, uint32_t addr){
  asm volatile("ldmatrix.sync.aligned.m8n8.x4.shared.b16 {%0,%1,%2,%3}, [%4];"
    : "=r"(r[0]), "=r"(r[1]), "=r"(r[2]), "=r"(r[3]) : "r"(addr));
}
__device__ __forceinline__ void bmma(float* c, const uint32_t* a, const uint32_t* b){
  asm volatile("mma.sync.aligned.m16n8k16.row.col.f32.bf16.bf16.f32 "
    "{%0,%1,%2,%3}, {%4,%5,%6,%7}, {%8,%9}, {%0,%1,%2,%3};"
    : "+f"(c[0]), "+f"(c[1]), "+f"(c[2]), "+f"(c[3])
    : "r"(a[0]), "r"(a[1]), "r"(a[2]), "r"(a[3]), "r"(b[0]), "r"(b[1]));
}
__device__ __forceinline__ void cp16(uint32_t d, const void* s){
  asm volatile("cp.async.cg.shared.global [%0], [%1], 16;" :: "r"(d), "l"(s));
}
__device__ __forceinline__ void cp_commit(){
  asm volatile("cp.async.commit_group;" ::: "memory");
}
template<int N> __device__ __forceinline__ void cp_wait(){
  asm volatile("cp.async.wait_group %0;" :: "n"(N) : "memory");
}

// ===========================================================================
// bf16 split (3-MMA) GEMM, 256 threads: C[128x128] = A * B^T (hi/lo inputs)
// BK=32, 2 stages, smem pitch 80 B.  (R7's proven kernel)
// ===========================================================================
#define BT_TILE  10240
#define BT_STAGE (4*BT_TILE)

template<class EPI>
__device__ __forceinline__ void bgemm_split(
    const __nv_bfloat16* __restrict__ Ah, const __nv_bfloat16* __restrict__ Al, int lda,
    const __nv_bfloat16* __restrict__ Bh, const __nv_bfloat16* __restrict__ Bl, int ldb,
    int m0, int n0, int k1, EPI&& epi)
{
  extern __shared__ __align__(16) char sd[];
  const int t = threadIdx.x, l = t & 31, w = t >> 5;
  const int wm = w & 3, wn = w >> 2;
  const int row = t >> 1, seg = (t & 1) * 16;
  const uint32_t sb = s2u(sd);
  const uint32_t soff = (uint32_t)row*80 + (t & 1)*32;

  const __nv_bfloat16* pAh = Ah + (size_t)(m0 + row)*lda + seg;
  const __nv_bfloat16* pAl = Al + (size_t)(m0 + row)*lda + seg;
  const __nv_bfloat16* pBh = Bh + (size_t)(n0 + row)*ldb + seg;
  const __nv_bfloat16* pBl = Bl + (size_t)(n0 + row)*ldb + seg;

  const int nch = k1 >> 5;
  auto load_stage = [&](int c){
    const int kb = c << 5;
    const uint32_t st = sb + (c & 1)*BT_STAGE + soff;
    cp16(st,               pAh + kb); cp16(st + 16,             pAh + kb + 8);
    cp16(st +   BT_TILE,   pAl + kb); cp16(st +   BT_TILE + 16, pAl + kb + 8);
    cp16(st + 2*BT_TILE,   pBh + kb); cp16(st + 2*BT_TILE + 16, pBh + kb + 8);
    cp16(st + 3*BT_TILE,   pBl + kb); cp16(st + 3*BT_TILE + 16, pBl + kb + 8);
  };
  load_stage(0);
  cp_commit();

  const uint32_t aoff = (uint32_t)(wm*32 + (l & 15))*80 + ((l >> 4) & 1)*16;
  const uint32_t boff = (uint32_t)(wn*64 + (l & 7) + ((l >> 4) & 1)*8)*80
                      + ((l >> 3) & 1)*16;

  float acc[2][8][4] = {};

  for (int c = 0; c < nch; c++){
    cp_wait<0>();
    __syncthreads();
    if (c + 1 < nch) load_stage(c + 1);
    cp_commit();

    const uint32_t base = sb + (c & 1)*BT_STAGE;
    const uint32_t uAh = base + aoff,             uAl = uAh + BT_TILE;
    const uint32_t uBh = base + 2*BT_TILE + boff, uBl = uBh + BT_TILE;

    #pragma unroll
    for (int kf = 0; kf < 2; kf++){
      const uint32_t ko = kf*32;
      uint32_t ah[2][4], al[2][4];
      ldsm4(ah[0], uAh + ko);  ldsm4(ah[1], uAh + ko + 16*80);
      ldsm4(al[0], uAl + ko);  ldsm4(al[1], uAl + ko + 16*80);
      #pragma unroll
      for (int nf2 = 0; nf2 < 4; nf2++){
        uint32_t bh[4], bl[4];
        ldsm4(bh, uBh + ko + nf2*16*80);
        ldsm4(bl, uBl + ko + nf2*16*80);
        #pragma unroll
        for (int mf = 0; mf < 2; mf++){
          bmma(acc[mf][2*nf2],     ah[mf], bh);
          bmma(acc[mf][2*nf2 + 1], ah[mf], bh + 2);
          bmma(acc[mf][2*nf2],     ah[mf], bl);
          bmma(acc[mf][2*nf2 + 1], ah[mf], bl + 2);
          bmma(acc[mf][2*nf2],     al[mf], bh);
          bmma(acc[mf][2*nf2 + 1], al[mf], bh + 2);
        }
      }
    }
  }
  epi(acc);
}

// ===========================================================================
// bf16 single GEMM, 256 threads: C[64 x 256] = A * B^T. BK=32, 2 stages.
// 8 warps = 2(M) x 4(N); warp tile 32 x 64. For out = P @ K.
// ===========================================================================
#define KA_T 5120                   // A: 64 rows * 80 B
#define KB_T 20480                  // B: 256 rows * 80 B
#define KST  (KA_T + KB_T)          // 25600; 2 stages = 51200

template<class EPI>
__device__ __forceinline__ void bgemm_out(
    const __nv_bfloat16* __restrict__ A, int lda,
    const __nv_bfloat16* __restrict__ B, int ldb,
    int m0, int n0, int k1, EPI&& epi)
{
  extern __shared__ __align__(16) char sd[];
  const int t = threadIdx.x, l = t & 31, w = t >> 5;
  const int wm = w & 1, wn = w >> 1;
  const uint32_t sb = s2u(sd);

  const int ar = t >> 2, as = (t & 3) * 8;     // row 0..63, 16B seg
  const uint32_t soA = (uint32_t)ar*80 + (t & 3)*16;
  const __nv_bfloat16* pA = A + (size_t)(m0 + ar)*lda + as;
  const __nv_bfloat16* pB = B + (size_t)(n0 + ar)*ldb + as;  // rows ar+64j

  const int nch = k1 >> 5;
  auto load_stage = [&](int c){
    const int kb = c << 5;
    const uint32_t st = sb + (c & 1)*KST;
    cp16(st + soA, pA + kb);
    #pragma unroll
    for (int j = 0; j < 4; j++)
      cp16(st + KA_T + soA + j*KA_T, pB + (size_t)j*64*ldb + kb);
  };
  load_stage(0);
  cp_commit();

  const uint32_t aoff = (uint32_t)(wm*32 + (l & 15))*80 + ((l >> 4) & 1)*16;
  const uint32_t boff = (uint32_t)(wn*64 + (l & 7) + ((l >> 4) & 1)*8)*80
                      + ((l >> 3) & 1)*16;

  float acc[2][8][4] = {};

  for (int c = 0; c < nch; c++){
    cp_wait<0>();
    __syncthreads();
    if (c + 1 < nch) load_stage(c + 1);
    cp_commit();

    const uint32_t base = sb + (c & 1)*KST;
    const uint32_t uA = base + aoff;
    const uint32_t uB = base + KA_T + boff;

    #pragma unroll
    for (int kf = 0; kf < 2; kf++){
      const uint32_t ko = kf*32;
      uint32_t a[2][4];
      ldsm4(a[0], uA + ko);
      ldsm4(a[1], uA + ko + 16*80);
      #pragma unroll
      for (int nf2 = 0; nf2 < 4; nf2++){
        uint32_t b[4];
        ldsm4(b, uB + ko + nf2*16*80);
        #pragma unroll
        for (int mf = 0; mf < 2; mf++){
          bmma(acc[mf][2*nf2],     a[mf], b);
          bmma(acc[mf][2*nf2 + 1], a[mf], b + 2);
        }
      }
    }
  }
  epi(acc);
}

// plain store epilogue (128x128 bf16 gemm)
__device__ __forceinline__ void epi_store(float (&acc)[2][8][4],
                                          float* __restrict__ C, int ldc,
                                          int m0, int n0)
{
  const int t = threadIdx.x, l = t & 31, w = t >> 5;
  const int wm = w & 3, wn = w >> 2;
  #pragma unroll
  for (int mf = 0; mf < 2; mf++){
    const int r0 = m0 + wm*32 + mf*16 + (l >> 2);
    #pragma unroll
    for (int nf = 0; nf < 8; nf++){
      const int cc = n0 + wn*64 + nf*8 + 2*(l & 3);
      *(float2*)&C[(size_t)r0*ldc + cc]     = make_float2(acc[mf][nf][0], acc[mf][nf][1]);
      *(float2*)&C[(size_t)(r0+8)*ldc + cc] = make_float2(acc[mf][nf][2], acc[mf][nf][3]);
    }
  }
}

// ---------------------------------------------------------------------------
// Kernels
// ---------------------------------------------------------------------------
__global__ void __launch_bounds__(256)
k_prep(const float* __restrict__ x, const float* __restrict__ W)
{
  const size_t nx = (size_t)NB*NCTX*DM/4, nw = (size_t)DM*DM/4;
  for (size_t i = blockIdx.x*256 + threadIdx.x; i < nx + nw; i += (size_t)gridDim.x*256){
    float4 v;
    __nv_bfloat16* hi; __nv_bfloat16* lo; size_t j;
    if (i < nx){ v = ((const float4*)x)[i];      hi = g_xhi; lo = g_xlo; j = i; }
    else       { v = ((const float4*)W)[i - nx]; hi = g_Whi; lo = g_Wlo; j = i - nx; }
    __nv_bfloat16 hx = __float2bfloat16_rn(v.x), hy = __float2bfloat16_rn(v.y);
    __nv_bfloat16 hz = __float2bfloat16_rn(v.z), hw = __float2bfloat16_rn(v.w);
    __nv_bfloat162 h01; h01.x = hx; h01.y = hy;
    __nv_bfloat162 h23; h23.x = hz; h23.y = hw;
    __nv_bfloat162 l01; l01.x = __float2bfloat16_rn(v.x - __bfloat162float(hx));
                        l01.y = __float2bfloat16_rn(v.y - __bfloat162float(hy));
    __nv_bfloat162 l23; l23.x = __float2bfloat16_rn(v.z - __bfloat162float(hz));
                        l23.y = __float2bfloat16_rn(v.w - __bfloat162float(hw));
    ((__nv_bfloat162*)hi)[2*j]     = h01;
    ((__nv_bfloat162*)hi)[2*j + 1] = h23;
    ((__nv_bfloat162*)lo)[2*j]     = l01;
    ((__nv_bfloat162*)lo)[2*j + 1] = l23;
  }
}

__global__ void __launch_bounds__(256, 2)
k_proj()
{ // K = x @ W^T -> Khi/Klo (bf16, K-major) and g_Ktb (bf16, transposed)
  const int n0 = blockIdx.x*128, m0 = blockIdx.y*128;
  bgemm_split(g_xhi, g_xlo, DM, g_Whi, g_Wlo, DM, m0, n0, DM,
    [&](float (&acc)[2][8][4]){
      const int t = threadIdx.x, l = t & 31, w = t >> 5;
      const int wm = w & 3, wn = w >> 2;
      #pragma unroll
      for (int mf = 0; mf < 2; mf++){
        const int r0 = m0 + wm*32 + mf*16 + (l >> 2);
        #pragma unroll
        for (int nf = 0; nf < 8; nf++){
          const int cc = n0 + wn*64 + nf*8 + 2*(l & 3);
          #pragma unroll
          for (int hh = 0; hh < 2; hh++){
            const int r = r0 + hh*8;
            const float v0 = acc[mf][nf][2*hh], v1 = acc[mf][nf][2*hh+1];
            __nv_bfloat16 h0 = __float2bfloat16_rn(v0), h1 = __float2bfloat16_rn(v1);
            __nv_bfloat162 hp; hp.x = h0; hp.y = h1;
            __nv_bfloat162 lp;
            lp.x = __float2bfloat16_rn(v0 - __bfloat162float(h0));
            lp.y = __float2bfloat16_rn(v1 - __bfloat162float(h1));
            const size_t ki = (size_t)r*DM + cc;
            *(__nv_bfloat162*)&g_Khi[ki] = hp;
            *(__nv_bfloat162*)&g_Klo[ki] = lp;
            g_Ktb[(size_t)cc    *LDKT + r] = h0;
            g_Ktb[(size_t)(cc+1)*LDKT + r] = h1;
          }
        }
      }
    });
}

__global__ void __launch_bounds__(256, 2)
k_scores()
{
  const int b  = blockIdx.z;
  const int n0 = blockIdx.x*128, m0 = blockIdx.y*128;
  if (n0 > m0) return;
  const size_t off = (size_t)b*NCTX*DM;
  float* Sb = g_S + (size_t)b*NCTX*NCTX;
  bgemm_split(g_xhi + off, g_xlo + off, DM, g_Khi + off, g_Klo + off, DM,
    m0, n0, DM,
    [&](float (&acc)[2][8][4]){ epi_store(acc, Sb, NCTX, m0, n0); });
}

// ---------------------------------------------------------------------------
// softmax: reads fp32 S, writes bf16 unnormalized exp to g_Pb,
// g_inv = 1/rowsum, zero-fill P to 128 boundary.
// ---------------------------------------------------------------------------
__device__ __forceinline__ float blk_sum(float v)
{
  __shared__ float sm[8];
  const int lane = threadIdx.x & 31, w = threadIdx.x >> 5;
  #pragma unroll
  for (int o = 16; o; o >>= 1) v += __shfl_xor_sync(0xffffffffu, v, o);
  if (lane == 0) sm[w] = v;
  __syncthreads();
  float r = sm[0];
  #pragma unroll
  for (int i = 1; i < 8; i++) r += sm[i];
  return r;
}

__global__ void __launch_bounds__(256)
k_softmax()
{
  const int row = blockIdx.x;
  const int q   = row & (NCTX - 1);
  const float* p = g_S + (size_t)row * NCTX;
  __nv_bfloat16* pb = g_Pb + (size_t)row * NCTX;
  const int len  = q + 1;
  const int len4 = len >> 2;
  const float4* p4 = (const float4*)p;
  __nv_bfloat162* pb2 = (__nv_bfloat162*)pb;

  float s = 0.f;
  for (int i = threadIdx.x; i < len4; i += 256){
    float4 v = p4[i];
    v.x = __expf(v.x); v.y = __expf(v.y);
    v.z = __expf(v.z); v.w = __expf(v.w);
    s += (v.x + v.y) + (v.z + v.w);
    __nv_bfloat162 e01; e01.x = __float2bfloat16_rn(v.x); e01.y = __float2bfloat16_rn(v.y);
    __nv_bfloat162 e23; e23.x = __float2bfloat16_rn(v.z); e23.y = __float2bfloat16_rn(v.w);
    pb2[2*i]     = e01;
    pb2[2*i + 1] = e23;
  }
  for (int i = (len4 << 2) + threadIdx.x; i < len; i += 256){
    float e = __expf(p[i]);
    s += e;
    pb[i] = __float2bfloat16_rn(e);
  }
  s = blk_sum(s);
  if (threadIdx.x == 0) g_inv[row] = 1.f / s;

  const int lenUp = (len + 127) & ~127;
  for (int i = len + threadIdx.x; i < lenUp; i += 256)
    pb[i] = __float2bfloat16_rn(0.f);
}

// ---------------------------------------------------------------------------
// out = x + (P @ K) * inv. bf16 single MMA. M_TILE=64, N_TILE=256.
// 128 equal CTAs: pair (i, 63-i) -> 130 chunks each. No atomics.
// ---------------------------------------------------------------------------
__global__ void __launch_bounds__(256, 2)
k_out_bf(const float* __restrict__ x, float* __restrict__ out)
{
  const int b    = blockIdx.z;
  const int n0   = blockIdx.x*256;      // 2 halves
  const int pair = blockIdx.y;          // 0..31
  const __nv_bfloat16* Pb = g_Pb  + (size_t)b*NCTX*NCTX;
  const __nv_bfloat16* Bt = g_Ktb + (size_t)b*NCTX;

  #pragma unroll
  for (int s = 0; s < 2; s++){
    const int i  = s ? (63 - pair) : pair;
    const int m0 = i*64;
    bgemm_out(Pb, NCTX, Bt, LDKT, m0, n0, (i + 1)*64,
      [&](float (&acc)[2][8][4]){
        const int t = threadIdx.x, l = t & 31, w = t >> 5;
        const int wm = w & 1, wn = w >> 1;
        #pragma unroll
        for (int mf = 0; mf < 2; mf++){
          const int r0 = m0 + wm*32 + mf*16 + (l >> 2);
          const float inv0 = g_inv[b*NCTX + r0];
          const float inv1 = g_inv[b*NCTX + r0 + 8];
          #pragma unroll
          for (int nf = 0; nf < 8; nf++){
            const int cc = n0 + wn*64 + nf*8 + 2*(l & 3);
            const size_t i0 = (size_t)b*NCTX*DM + (size_t)r0*DM + cc;
            const size_t i1 = i0 + (size_t)8*DM;
            *(float2*)&out[i0] = make_float2(acc[mf][nf][0]*inv0 + x[i0],
                                             acc[mf][nf][1]*inv0 + x[i0+1]);
            *(float2*)&out[i1] = make_float2(acc[mf][nf][2]*inv1 + x[i1],
                                             acc[mf][nf][3]*inv1 + x[i1+1]);
          }
        }
      });
  }
}

// ---------------------------------------------------------------------------
extern "C" void kernel_launch(void* const* d_in, const int* in_sizes, int n_in,
                              void* d_out, int out_size)
{
  const float* x = (const float*)d_in[0];
  const float* W = (const float*)d_in[1];
  float* out = (float*)d_out;

  const int SMEM_BF  = 2 * BT_STAGE;     // 81920
  const int SMEM_OUT = 2 * KST;          // 51200
  cudaFuncSetAttribute(k_proj,   cudaFuncAttributeMaxDynamicSharedMemorySize, SMEM_BF);
  cudaFuncSetAttribute(k_scores, cudaFuncAttributeMaxDynamicSharedMemorySize, SMEM_BF);
  cudaFuncSetAttribute(k_out_bf, cudaFuncAttributeMaxDynamicSharedMemorySize, SMEM_OUT);

  k_prep   <<<1184, 256>>>(x, W);
  k_proj   <<<dim3(4, 64),      256, SMEM_BF>>>();
  k_scores <<<dim3(32, 32, NB), 256, SMEM_BF>>>();
  k_softmax<<<NB * NCTX, 256>>>();
  k_out_bf <<<dim3(2, 32, NB),  256, SMEM_OUT>>>(x, out);
}

// round 12
// speedup vs baseline: 1.1834x; 1.0497x over previous
#include <cuda_runtime.h>
#include <cuda_bf16.h>
#include <cuda_fp16.h>
#include <cstdint>

#define NCTX 4096
#define DM   512
#define NB   2
#define LDKT (NB*NCTX)

// Scratch
__device__ __nv_bfloat16 g_xhi[(size_t)NB*NCTX*DM];
__device__ __nv_bfloat16 g_xlo[(size_t)NB*NCTX*DM];
__device__ __nv_bfloat16 g_Whi[(size_t)DM*DM];
__device__ __nv_bfloat16 g_Wlo[(size_t)DM*DM];
__device__ __nv_bfloat16 g_Khi[(size_t)NB*NCTX*DM];
__device__ __nv_bfloat16 g_Klo[(size_t)NB*NCTX*DM];
__device__ __half        g_Ktb[(size_t)DM*NB*NCTX];   // fp16 K^T
__device__ float         g_S  [(size_t)NB*NCTX*NCTX]; // fp32 scores
__device__ __half        g_Pb [(size_t)NB*NCTX*NCTX]; // fp16 exp(s-m), unnormalized
__device__ float         g_inv[(size_t)NB*NCTX];      // 1 / rowsum(exp)

// ---------------------------------------------------------------------------
// helpers
// ---------------------------------------------------------------------------
__device__ __forceinline__ uint32_t s2u(const void* p){
  uint32_t a;
  asm("{ .reg .u64 t; cvta.to.shared.u64 t, %1; cvt.u32.u64 %0, t; }" : "=r"(a) : "l"(p));
  return a;
}
__device__ __forceinline__ void ldsm4(uint32_t* r, uint32_t addr){
  asm volatile("ldmatrix.sync.aligned.m8n8.x4.shared.b16 {%0,%1,%2,%3}, [%4];"
    : "=r"(r[0]), "=r"(r[1]), "=r"(r[2]), "=r"(r[3]) : "r"(addr));
}
__device__ __forceinline__ void bmma(float* c, const uint32_t* a, const uint32_t* b){
  asm volatile("mma.sync.aligned.m16n8k16.row.col.f32.bf16.bf16.f32 "
    "{%0,%1,%2,%3}, {%4,%5,%6,%7}, {%8,%9}, {%0,%1,%2,%3};"
    : "+f"(c[0]), "+f"(c[1]), "+f"(c[2]), "+f"(c[3])
    : "r"(a[0]), "r"(a[1]), "r"(a[2]), "r"(a[3]), "r"(b[0]), "r"(b[1]));
}
__device__ __forceinline__ void hmma(float* c, const uint32_t* a, const uint32_t* b){
  asm volatile("mma.sync.aligned.m16n8k16.row.col.f32.f16.f16.f32 "
    "{%0,%1,%2,%3}, {%4,%5,%6,%7}, {%8,%9}, {%0,%1,%2,%3};"
    : "+f"(c[0]), "+f"(c[1]), "+f"(c[2]), "+f"(c[3])
    : "r"(a[0]), "r"(a[1]), "r"(a[2]), "r"(a[3]), "r"(b[0]), "r"(b[1]));
}
__device__ __forceinline__ void cp16(uint32_t d, const void* s){
  asm volatile("cp.async.cg.shared.global [%0], [%1], 16;" :: "r"(d), "l"(s));
}
__device__ __forceinline__ void cp_commit(){
  asm volatile("cp.async.commit_group;" ::: "memory");
}
template<int N> __device__ __forceinline__ void cp_wait(){
  asm volatile("cp.async.wait_group %0;" :: "n"(N) : "memory");
}

// ===========================================================================
// bf16 split (3-MMA) GEMM, 256 threads: C[128x128] = A * B^T (hi/lo inputs)
// BK=32, 2 stages, smem pitch 80 B.  (proven kernel)
// ===========================================================================
#define BT_TILE  10240
#define BT_STAGE (4*BT_TILE)

template<class EPI>
__device__ __forceinline__ void bgemm_split(
    const __nv_bfloat16* __restrict__ Ah, const __nv_bfloat16* __restrict__ Al, int lda,
    const __nv_bfloat16* __restrict__ Bh, const __nv_bfloat16* __restrict__ Bl, int ldb,
    int m0, int n0, int k1, EPI&& epi)
{
  extern __shared__ __align__(16) char sd[];
  const int t = threadIdx.x, l = t & 31, w = t >> 5;
  const int wm = w & 3, wn = w >> 2;
  const int row = t >> 1, seg = (t & 1) * 16;
  const uint32_t sb = s2u(sd);
  const uint32_t soff = (uint32_t)row*80 + (t & 1)*32;

  const __nv_bfloat16* pAh = Ah + (size_t)(m0 + row)*lda + seg;
  const __nv_bfloat16* pAl = Al + (size_t)(m0 + row)*lda + seg;
  const __nv_bfloat16* pBh = Bh + (size_t)(n0 + row)*ldb + seg;
  const __nv_bfloat16* pBl = Bl + (size_t)(n0 + row)*ldb + seg;

  const int nch = k1 >> 5;
  auto load_stage = [&](int c){
    const int kb = c << 5;
    const uint32_t st = sb + (c & 1)*BT_STAGE + soff;
    cp16(st,               pAh + kb); cp16(st + 16,             pAh + kb + 8);
    cp16(st +   BT_TILE,   pAl + kb); cp16(st +   BT_TILE + 16, pAl + kb + 8);
    cp16(st + 2*BT_TILE,   pBh + kb); cp16(st + 2*BT_TILE + 16, pBh + kb + 8);
    cp16(st + 3*BT_TILE,   pBl + kb); cp16(st + 3*BT_TILE + 16, pBl + kb + 8);
  };
  load_stage(0);
  cp_commit();

  const uint32_t aoff = (uint32_t)(wm*32 + (l & 15))*80 + ((l >> 4) & 1)*16;
  const uint32_t boff = (uint32_t)(wn*64 + (l & 7) + ((l >> 4) & 1)*8)*80
                      + ((l >> 3) & 1)*16;

  float acc[2][8][4] = {};

  for (int c = 0; c < nch; c++){
    cp_wait<0>();
    __syncthreads();
    if (c + 1 < nch) load_stage(c + 1);
    cp_commit();

    const uint32_t base = sb + (c & 1)*BT_STAGE;
    const uint32_t uAh = base + aoff,             uAl = uAh + BT_TILE;
    const uint32_t uBh = base + 2*BT_TILE + boff, uBl = uBh + BT_TILE;

    #pragma unroll
    for (int kf = 0; kf < 2; kf++){
      const uint32_t ko = kf*32;
      uint32_t ah[2][4], al[2][4];
      ldsm4(ah[0], uAh + ko);  ldsm4(ah[1], uAh + ko + 16*80);
      ldsm4(al[0], uAl + ko);  ldsm4(al[1], uAl + ko + 16*80);
      #pragma unroll
      for (int nf2 = 0; nf2 < 4; nf2++){
        uint32_t bh[4], bl[4];
        ldsm4(bh, uBh + ko + nf2*16*80);
        ldsm4(bl, uBl + ko + nf2*16*80);
        #pragma unroll
        for (int mf = 0; mf < 2; mf++){
          bmma(acc[mf][2*nf2],     ah[mf], bh);
          bmma(acc[mf][2*nf2 + 1], ah[mf], bh + 2);
          bmma(acc[mf][2*nf2],     ah[mf], bl);
          bmma(acc[mf][2*nf2 + 1], ah[mf], bl + 2);
          bmma(acc[mf][2*nf2],     al[mf], bh);
          bmma(acc[mf][2*nf2 + 1], al[mf], bh + 2);
        }
      }
    }
  }
  epi(acc);
}

// ===========================================================================
// fp16 single GEMM, 256 threads: C[64 x 128] = A * B^T. BK=32, 2 stages.
// 8 warps = 2(M) x 4(N); warp tile 32 x 32. For out = P @ K.
// ===========================================================================
#define KA_T 5120                   // A: 64 rows * 80 B
#define KB_T 10240                  // B: 128 rows * 80 B
#define KST  (KA_T + KB_T)          // 15360; 2 stages = 30720

template<class EPI>
__device__ __forceinline__ void hgemm_out(
    const __half* __restrict__ A, int lda,
    const __half* __restrict__ B, int ldb,
    int m0, int n0, int k1, EPI&& epi)
{
  extern __shared__ __align__(16) char sd[];
  const int t = threadIdx.x, l = t & 31, w = t >> 5;
  const int wm = w & 1, wn = w >> 1;
  const uint32_t sb = s2u(sd);

  const int ar = t >> 2, as = (t & 3) * 8;     // row 0..63, 16B seg
  const uint32_t soA = (uint32_t)ar*80 + (t & 3)*16;
  const __half* pA = A + (size_t)(m0 + ar)*lda + as;
  const __half* pB = B + (size_t)(n0 + ar)*ldb + as;   // rows ar, ar+64

  const int nch = k1 >> 5;
  auto load_stage = [&](int c){
    const int kb = c << 5;
    const uint32_t st = sb + (c & 1)*KST;
    cp16(st + soA, pA + kb);
    cp16(st + KA_T + soA,        pB + kb);
    cp16(st + KA_T + soA + KA_T, pB + (size_t)64*ldb + kb);
  };
  load_stage(0);
  cp_commit();

  const uint32_t aoff = (uint32_t)(wm*32 + (l & 15))*80 + ((l >> 4) & 1)*16;
  const uint32_t boff = (uint32_t)(wn*32 + (l & 7) + ((l >> 4) & 1)*8)*80
                      + ((l >> 3) & 1)*16;

  float acc[2][4][4] = {};

  for (int c = 0; c < nch; c++){
    cp_wait<0>();
    __syncthreads();
    if (c + 1 < nch) load_stage(c + 1);
    cp_commit();

    const uint32_t base = sb + (c & 1)*KST;
    const uint32_t uA = base + aoff;
    const uint32_t uB = base + KA_T + boff;

    #pragma unroll
    for (int kf = 0; kf < 2; kf++){
      const uint32_t ko = kf*32;
      uint32_t a[2][4];
      ldsm4(a[0], uA + ko);
      ldsm4(a[1], uA + ko + 16*80);
      #pragma unroll
      for (int nf2 = 0; nf2 < 2; nf2++){
        uint32_t b[4];
        ldsm4(b, uB + ko + nf2*16*80);
        #pragma unroll
        for (int mf = 0; mf < 2; mf++){
          hmma(acc[mf][2*nf2],     a[mf], b);
          hmma(acc[mf][2*nf2 + 1], a[mf], b + 2);
        }
      }
    }
  }
  epi(acc);
}

// plain store epilogue (128x128 bf16 gemm)
__device__ __forceinline__ void epi_store(float (&acc)[2][8][4],
                                          float* __restrict__ C, int ldc,
                                          int m0, int n0)
{
  const int t = threadIdx.x, l = t & 31, w = t >> 5;
  const int wm = w & 3, wn = w >> 2;
  #pragma unroll
  for (int mf = 0; mf < 2; mf++){
    const int r0 = m0 + wm*32 + mf*16 + (l >> 2);
    #pragma unroll
    for (int nf = 0; nf < 8; nf++){
      const int cc = n0 + wn*64 + nf*8 + 2*(l & 3);
      *(float2*)&C[(size_t)r0*ldc + cc]     = make_float2(acc[mf][nf][0], acc[mf][nf][1]);
      *(float2*)&C[(size_t)(r0+8)*ldc + cc] = make_float2(acc[mf][nf][2], acc[mf][nf][3]);
    }
  }
}

// ---------------------------------------------------------------------------
// Kernels
// ---------------------------------------------------------------------------
__global__ void __launch_bounds__(256)
k_prep(const float* __restrict__ x, const float* __restrict__ W)
{
  const size_t nx = (size_t)NB*NCTX*DM/4, nw = (size_t)DM*DM/4;
  for (size_t i = blockIdx.x*256 + threadIdx.x; i < nx + nw; i += (size_t)gridDim.x*256){
    float4 v;
    __nv_bfloat16* hi; __nv_bfloat16* lo; size_t j;
    if (i < nx){ v = ((const float4*)x)[i];      hi = g_xhi; lo = g_xlo; j = i; }
    else       { v = ((const float4*)W)[i - nx]; hi = g_Whi; lo = g_Wlo; j = i - nx; }
    __nv_bfloat16 hx = __float2bfloat16_rn(v.x), hy = __float2bfloat16_rn(v.y);
    __nv_bfloat16 hz = __float2bfloat16_rn(v.z), hw = __float2bfloat16_rn(v.w);
    __nv_bfloat162 h01; h01.x = hx; h01.y = hy;
    __nv_bfloat162 h23; h23.x = hz; h23.y = hw;
    __nv_bfloat162 l01; l01.x = __float2bfloat16_rn(v.x - __bfloat162float(hx));
                        l01.y = __float2bfloat16_rn(v.y - __bfloat162float(hy));
    __nv_bfloat162 l23; l23.x = __float2bfloat16_rn(v.z - __bfloat162float(hz));
                        l23.y = __float2bfloat16_rn(v.w - __bfloat162float(hw));
    ((__nv_bfloat162*)hi)[2*j]     = h01;
    ((__nv_bfloat162*)hi)[2*j + 1] = h23;
    ((__nv_bfloat162*)lo)[2*j]     = l01;
    ((__nv_bfloat162*)lo)[2*j + 1] = l23;
  }
}

__global__ void __launch_bounds__(256, 2)
k_proj()
{ // K = x @ W^T -> Khi/Klo (bf16, K-major) and g_Ktb (fp16, transposed)
  const int n0 = blockIdx.x*128, m0 = blockIdx.y*128;
  bgemm_split(g_xhi, g_xlo, DM, g_Whi, g_Wlo, DM, m0, n0, DM,
    [&](float (&acc)[2][8][4]){
      const int t = threadIdx.x, l = t & 31, w = t >> 5;
      const int wm = w & 3, wn = w >> 2;
      #pragma unroll
      for (int mf = 0; mf < 2; mf++){
        const int r0 = m0 + wm*32 + mf*16 + (l >> 2);
        #pragma unroll
        for (int nf = 0; nf < 8; nf++){
          const int cc = n0 + wn*64 + nf*8 + 2*(l & 3);
          #pragma unroll
          for (int hh = 0; hh < 2; hh++){
            const int r = r0 + hh*8;
            const float v0 = acc[mf][nf][2*hh], v1 = acc[mf][nf][2*hh+1];
            __nv_bfloat16 h0 = __float2bfloat16_rn(v0), h1 = __float2bfloat16_rn(v1);
            __nv_bfloat162 hp; hp.x = h0; hp.y = h1;
            __nv_bfloat162 lp;
            lp.x = __float2bfloat16_rn(v0 - __bfloat162float(h0));
            lp.y = __float2bfloat16_rn(v1 - __bfloat162float(h1));
            const size_t ki = (size_t)r*DM + cc;
            *(__nv_bfloat162*)&g_Khi[ki] = hp;
            *(__nv_bfloat162*)&g_Klo[ki] = lp;
            g_Ktb[(size_t)cc    *LDKT + r] = __float2half_rn(v0);
            g_Ktb[(size_t)(cc+1)*LDKT + r] = __float2half_rn(v1);
          }
        }
      }
    });
}

__global__ void __launch_bounds__(256, 2)
k_scores()
{
  const int b  = blockIdx.z;
  const int n0 = blockIdx.x*128, m0 = blockIdx.y*128;
  if (n0 > m0) return;
  const size_t off = (size_t)b*NCTX*DM;
  float* Sb = g_S + (size_t)b*NCTX*NCTX;
  bgemm_split(g_xhi + off, g_xlo + off, DM, g_Khi + off, g_Klo + off, DM,
    m0, n0, DM,
    [&](float (&acc)[2][8][4]){ epi_store(acc, Sb, NCTX, m0, n0); });
}

// ---------------------------------------------------------------------------
// softmax: max-subtracted, writes fp16 exp(s-m) to g_Pb, g_inv = 1/rowsum,
// zero-fills P to the 128 boundary.
// ---------------------------------------------------------------------------
__device__ __forceinline__ float blk_red(float v, bool is_max)
{
  __shared__ float sm[8];
  const int lane = threadIdx.x & 31, w = threadIdx.x >> 5;
  #pragma unroll
  for (int o = 16; o; o >>= 1){
    float u = __shfl_xor_sync(0xffffffffu, v, o);
    v = is_max ? fmaxf(v, u) : v + u;
  }
  if (lane == 0) sm[w] = v;
  __syncthreads();
  float r = sm[0];
  #pragma unroll
  for (int i = 1; i < 8; i++) r = is_max ? fmaxf(r, sm[i]) : r + sm[i];
  __syncthreads();
  return r;
}

__global__ void __launch_bounds__(256)
k_softmax()
{
  const int row = blockIdx.x;
  const int q   = row & (NCTX - 1);
  const float* p = g_S + (size_t)row * NCTX;
  __half* pb = g_Pb + (size_t)row * NCTX;
  const int len  = q + 1;
  const int len4 = len >> 2;
  const float4* p4 = (const float4*)p;
  __half2* pb2 = (__half2*)pb;

  float m = -1e30f;
  for (int i = threadIdx.x; i < len4; i += 256){
    float4 v = p4[i];
    m = fmaxf(m, fmaxf(fmaxf(v.x, v.y), fmaxf(v.z, v.w)));
  }
  for (int i = (len4 << 2) + threadIdx.x; i < len; i += 256) m = fmaxf(m, p[i]);
  m = blk_red(m, true);

  float s = 0.f;
  for (int i = threadIdx.x; i < len4; i += 256){
    float4 v = p4[i];
    v.x = __expf(v.x - m); v.y = __expf(v.y - m);
    v.z = __expf(v.z - m); v.w = __expf(v.w - m);
    s += (v.x + v.y) + (v.z + v.w);
    pb2[2*i]     = __floats2half2_rn(v.x, v.y);
    pb2[2*i + 1] = __floats2half2_rn(v.z, v.w);
  }
  for (int i = (len4 << 2) + threadIdx.x; i < len; i += 256){
    float e = __expf(p[i] - m);
    s += e;
    pb[i] = __float2half_rn(e);
  }
  s = blk_red(s, false);
  if (threadIdx.x == 0) g_inv[row] = 1.f / s;

  const int lenUp = (len + 127) & ~127;
  for (int i = len + threadIdx.x; i < lenUp; i += 256)
    pb[i] = __float2half_rn(0.f);
}

// ---------------------------------------------------------------------------
// out = x + (P @ K) * inv. fp16 single MMA. M_TILE=64, N_TILE=128.
// 256 equal CTAs: pair (i, 63-i) x 4 n-strips. No atomics.
// ---------------------------------------------------------------------------
__global__ void __launch_bounds__(256, 2)
k_out_h(const float* __restrict__ x, float* __restrict__ out)
{
  const int b    = blockIdx.z;
  const int n0   = blockIdx.x*128;      // 4 strips
  const int pair = blockIdx.y;          // 0..31
  const __half* Pb = g_Pb  + (size_t)b*NCTX*NCTX;
  const __half* Bt = g_Ktb + (size_t)b*NCTX;

  #pragma unroll
  for (int s = 0; s < 2; s++){
    const int i  = s ? (63 - pair) : pair;
    const int m0 = i*64;
    hgemm_out(Pb, NCTX, Bt, LDKT, m0, n0, (i + 1)*64,
      [&](float (&acc)[2][4][4]){
        const int t = threadIdx.x, l = t & 31, w = t >> 5;
        const int wm = w & 1, wn = w >> 1;
        #pragma unroll
        for (int mf = 0; mf < 2; mf++){
          const int r0 = m0 + wm*32 + mf*16 + (l >> 2);
          const float inv0 = g_inv[b*NCTX + r0];
          const float inv1 = g_inv[b*NCTX + r0 + 8];
          #pragma unroll
          for (int nf = 0; nf < 4; nf++){
            const int cc = n0 + wn*32 + nf*8 + 2*(l & 3);
            const size_t i0 = (size_t)b*NCTX*DM + (size_t)r0*DM + cc;
            const size_t i1 = i0 + (size_t)8*DM;
            *(float2*)&out[i0] = make_float2(acc[mf][nf][0]*inv0 + x[i0],
                                             acc[mf][nf][1]*inv0 + x[i0+1]);
            *(float2*)&out[i1] = make_float2(acc[mf][nf][2]*inv1 + x[i1],
                                             acc[mf][nf][3]*inv1 + x[i1+1]);
          }
        }
      });
  }
}

// ---------------------------------------------------------------------------
extern "C" void kernel_launch(void* const* d_in, const int* in_sizes, int n_in,
                              void* d_out, int out_size)
{
  const float* x = (const float*)d_in[0];
  const float* W = (const float*)d_in[1];
  float* out = (float*)d_out;

  const int SMEM_BF  = 2 * BT_STAGE;     // 81920
  const int SMEM_OUT = 2 * KST;          // 30720
  cudaFuncSetAttribute(k_proj,   cudaFuncAttributeMaxDynamicSharedMemorySize, SMEM_BF);
  cudaFuncSetAttribute(k_scores, cudaFuncAttributeMaxDynamicSharedMemorySize, SMEM_BF);
  cudaFuncSetAttribute(k_out_h,  cudaFuncAttributeMaxDynamicSharedMemorySize, SMEM_OUT);

  k_prep   <<<1184, 256>>>(x, W);
  k_proj   <<<dim3(4, 64),      256, SMEM_BF>>>();
  k_scores <<<dim3(32, 32, NB), 256, SMEM_BF>>>();
  k_softmax<<<NB * NCTX, 256>>>();
  k_out_h  <<<dim3(4, 32, NB),  256, SMEM_OUT>>>(x, out);
}